// round 13
// baseline (speedup 1.0000x reference)
#include <cuda_runtime.h>
#include <math.h>
#include <stdint.h>

#define Bn 32
#define Ln 8192
#define Cn 64
#define Mn 64
#define Jn 128          // 2*Mn (cos/sin rows)
#define JG 192          // Jn + Cn
#define NCH 16          // stage-1 K chunks (K=512 each) -> 512 CTAs, single wave
#define TWOPI_8192 0.00076699039394282058f   // 2*pi/8192

// ---- scratch (device globals; no allocation allowed) ----
__device__ float g_b1frag[8 * 64 * 32 * 4];     // stage-1 A frags [mt][ks][lane][q], ch-independent (256KB)
__device__ float g_b3frag[8 * 16 * 32 * 4];     // stage-3 A frags [mt][ks][lane][q], lt-independent (64KB)
__device__ float g_Aw[Mn * Cn * Cn];            // [k][i][o] = alpha_k * Wr
__device__ float g_Bw[Mn * Cn * Cn];            // [k][i][o] = alpha_k * Wi
__device__ float g_Pp[NCH * Bn * Jn * Cn];      // stage-1 partials [ch][b][j][c] (local basis)
__device__ float g_G[Bn * JG * Cn];             // stage-3 B operand [b][j][o] (fp32)

// ---------------- helpers ----------------
__device__ __forceinline__ float totf32(float x) {
    uint32_t u;
    asm("cvt.rn.tf32.f32 %0, %1;" : "=r"(u) : "f"(x));
    return __uint_as_float(u);
}
__device__ __forceinline__ float4 totf32_4(float4 v) {
    v.x = totf32(v.x); v.y = totf32(v.y); v.z = totf32(v.z); v.w = totf32(v.w);
    return v;
}
__device__ __forceinline__ uint32_t fau(float x) { return __float_as_uint(x); }

// m16n8k8 tf32 mma
__device__ __forceinline__ void mma_t32(float c[4], const uint32_t a[4],
                                        uint32_t b0, uint32_t b1) {
    asm volatile(
        "mma.sync.aligned.m16n8k8.row.col.f32.tf32.tf32.f32 "
        "{%0,%1,%2,%3}, {%4,%5,%6,%7}, {%8,%9}, {%0,%1,%2,%3};"
        : "+f"(c[0]), "+f"(c[1]), "+f"(c[2]), "+f"(c[3])
        : "r"(a[0]), "r"(a[1]), "r"(a[2]), "r"(a[3]), "r"(b0), "r"(b1));
}

// ---------------------------------------------------------------------------
// Merged prep.  [0,256): stage-1 frags (local ll<512); [256,320): stage-3
// basisR frags (local r<128); [320,576): prepW; [576,608): pwfill.
// ---------------------------------------------------------------------------
__global__ void __launch_bounds__(256) k_prep(const float* __restrict__ wr,
                                              const float* __restrict__ wi,
                                              const float* __restrict__ pw) {
    __shared__ float t0[32][33], t1[32][33];
    int bx = blockIdx.x;
    if (bx < 256) {
        // stage-1 A frags: A[j][ll], j = mt*16+row, ll = ks*8+col (ll local to chunk)
        int g = bx * 256 + threadIdx.x;              // 65536
        int q = g & 3, lane = (g >> 2) & 31, ks = (g >> 7) & 63, mt = g >> 13;
        int j = mt * 16 + (lane >> 2) + (q & 1) * 8;
        int ll = ks * 8 + (lane & 3) + ((q >> 1) & 1) * 4;
        int m = ((j >> 1) * ll) & (Ln - 1);
        float th = (float)m * TWOPI_8192;
        float s, c; __sincosf(th, &s, &c);
        g_b1frag[g] = totf32((j & 1) ? s : c);
    } else if (bx < 320) {
        // stage-3 basisR frags: A[r][j], r = mt*16+row (r local to 128-tile)
        int g = (bx - 256) * 256 + threadIdx.x;      // 16384
        int q = g & 3, lane = (g >> 2) & 31, ks = (g >> 7) & 15, mt = g >> 11;
        int r = mt * 16 + (lane >> 2) + (q & 1) * 8;
        int j = ks * 8 + (lane & 3) + ((q >> 1) & 1) * 4;
        int m = ((j >> 1) * r) & (Ln - 1);
        float th = (float)m * TWOPI_8192;
        float s, c; __sincosf(th, &s, &c);
        g_b3frag[g] = totf32((j & 1) ? s : c);
    } else if (bx < 576) {
        int tile = bx - 320;
        int rc0 = (tile >> 1) * 32, k0 = (tile & 1) * 32;
        int tx = threadIdx.x & 31, ty = threadIdx.x >> 5;
#pragma unroll
        for (int rr = ty; rr < 32; rr += 8) {
            t0[rr][tx] = wr[(rc0 + rr) * 64 + k0 + tx];
            t1[rr][tx] = wi[(rc0 + rr) * 64 + k0 + tx];
        }
        __syncthreads();
#pragma unroll
        for (int kk = ty; kk < 32; kk += 8) {
            int k = k0 + kk;
            float alpha = (k == 0 ? 1.0f : 2.0f) / (float)Ln;
            g_Aw[k * 4096 + rc0 + tx] = alpha * t0[tx][kk];
            g_Bw[k * 4096 + rc0 + tx] = alpha * t1[tx][kk];
        }
    } else {
        int b = bx - 576, t = threadIdx.x;
#pragma unroll
        for (int i = 0; i < 16; i++) {
            int idx = t + i * 256;
            int o = idx & 63, ic = idx >> 6;
            g_G[(b * JG + Jn + ic) * Cn + o] = pw[o * Cn + ic];
        }
    }
}

// ---------------------------------------------------------------------------
// Stage 1: local-basis partials; K=512 per block.  (R12 inner loop; A-frag
// table is now chunk-independent.)
// ---------------------------------------------------------------------------
__global__ void __launch_bounds__(256) k_dft(const float* __restrict__ x) {
    int ch = blockIdx.x, b = blockIdx.y;
    __shared__ float Xs[2][32 * 72];
    int t = threadIdx.x, w = t >> 5, lane = t & 31;
    int g = lane >> 2, tg = lane & 3;
    int row0 = t >> 4, c4 = t & 15;

    float c[8][4];
#pragma unroll
    for (int nt = 0; nt < 8; nt++)
#pragma unroll
        for (int q = 0; q < 4; q++) c[nt][q] = 0.0f;

    const float4* ap = (const float4*)g_b1frag + ((size_t)(w * 64) * 32 + lane);
    const float* xb = x + (size_t)b * Ln * Cn + (size_t)ch * 512 * Cn;

    {
        float4 v0 = totf32_4(*(const float4*)&xb[row0 * Cn + c4 * 4]);
        float4 v1 = totf32_4(*(const float4*)&xb[(row0 + 16) * Cn + c4 * 4]);
        *(float4*)&Xs[0][row0 * 72 + c4 * 4] = v0;
        *(float4*)&Xs[0][(row0 + 16) * 72 + c4 * 4] = v1;
    }
    __syncthreads();

    for (int kc = 0; kc < 16; kc++) {
        int cur = kc & 1;
        float4 n0, n1;
        if (kc < 15) {
            const float* xn = xb + (kc + 1) * 32 * Cn;
            n0 = *(const float4*)&xn[row0 * Cn + c4 * 4];
            n1 = *(const float4*)&xn[(row0 + 16) * Cn + c4 * 4];
        }
        float4 af[4];
#pragma unroll
        for (int s = 0; s < 4; s++) af[s] = ap[(kc * 4 + s) * 32];
#pragma unroll
        for (int ks4 = 0; ks4 < 4; ks4++) {
            uint32_t a[4] = { fau(af[ks4].x), fau(af[ks4].y),
                              fau(af[ks4].z), fau(af[ks4].w) };
            int kr0 = ks4 * 8 + tg;
#pragma unroll
            for (int nt = 0; nt < 8; nt++) {
                uint32_t b0 = fau(Xs[cur][kr0 * 72 + nt * 8 + g]);
                uint32_t b1 = fau(Xs[cur][(kr0 + 4) * 72 + nt * 8 + g]);
                mma_t32(c[nt], a, b0, b1);
            }
        }
        if (kc < 15) {
            *(float4*)&Xs[cur ^ 1][row0 * 72 + c4 * 4] = totf32_4(n0);
            *(float4*)&Xs[cur ^ 1][(row0 + 16) * 72 + c4 * 4] = totf32_4(n1);
        }
        __syncthreads();
    }

    float* dst = g_Pp + ((size_t)(ch * Bn + b) * Jn) * Cn;
    int j0 = w * 16 + g;
#pragma unroll
    for (int nt = 0; nt < 8; nt++) {
        *(float2*)&dst[j0 * Cn + nt * 8 + 2 * tg]       = make_float2(c[nt][0], c[nt][1]);
        *(float2*)&dst[(j0 + 8) * Cn + nt * 8 + 2 * tg] = make_float2(c[nt][2], c[nt][3]);
    }
}

// ---------------------------------------------------------------------------
// Stage 2: rotate local partials to global basis, reduce, complex mix.
// theta(ch,k) = 2*pi*((k*ch)&15)/16.
// ---------------------------------------------------------------------------
__global__ void k_mix() {
    int k = blockIdx.x, b = blockIdx.y, o = threadIdx.x;
    __shared__ float P0[Cn], P1[Cn];
    __shared__ float2 rt[16];
    if (o < 16) {
        float s, c; __sincosf((float)o * 0.39269908169872415481f, &s, &c);
        rt[o] = make_float2(c, s);
    }
    __syncthreads();
    float p0 = 0.0f, p1 = 0.0f;
#pragma unroll 4
    for (int ch = 0; ch < NCH; ch++) {
        const float* src = g_Pp + ((size_t)(ch * Bn + b) * Jn + 2 * k) * Cn;
        float v0 = src[o], v1 = src[Cn + o];
        float2 r = rt[(k * ch) & 15];
        p0 += r.x * v0 - r.y * v1;
        p1 += r.y * v0 + r.x * v1;
    }
    P0[o] = p0; P1[o] = p1;
    __syncthreads();
    float gr = 0.0f, gi = 0.0f;
#pragma unroll 8
    for (int i = 0; i < Cn; i++) {
        float a  = g_Aw[(k * Cn + i) * Cn + o];
        float bb = g_Bw[(k * Cn + i) * Cn + o];
        float pr = P0[i], pi = P1[i];
        gr += pr * a + pi * bb;
        gi += pi * a - pr * bb;
    }
    g_G[(b * JG + 2 * k) * Cn + o]     = gr;
    g_G[(b * JG + 2 * k + 1) * Cn + o] = gi;
}

// ---------------------------------------------------------------------------
// Stage 3: out[l=128][o=64] = sum_j basisR[r][j]*G'[j][o] + x-part + bias.
// G' = per-lt twiddle rotation of G applied during staging.
// Warp grid 4(M) x 2(N): B pair feeds 2 MMAs (B-LDS halved).
// ---------------------------------------------------------------------------
__global__ void __launch_bounds__(256) k_out(const float* __restrict__ x,
                                             const float* __restrict__ bias,
                                             float* __restrict__ out) {
    int lt = blockIdx.x, b = blockIdx.y;
    extern __shared__ __align__(16) float sm[];
    float* Gs = sm;                                  // [192][72]
    float* As = sm + 192 * 72;                       // [128][76]
    int t = threadIdx.x, w = t >> 5, lane = t & 31;
    int wm = w & 3, wn = w >> 2;
    int g = lane >> 2, tg = lane & 3;

    {   // stage G with twiddle rotation: theta_k = 2*pi*((k*lt)&63)/64
        const float4* src = (const float4*)(g_G + (size_t)b * JG * Cn);
#pragma unroll
        for (int i = 0; i < 4; i++) {                // 64 k-pairs x 16 col-chunks
            int idx = t + i * 256;
            int k = idx >> 4, cc = idx & 15;
            float4 vr = src[(2 * k) * 16 + cc];
            float4 vi = src[(2 * k + 1) * 16 + cc];
            int m = ((k * lt) & 63) * 128;
            float s, c; __sincosf((float)m * TWOPI_8192, &s, &c);
            float4 g0, g1;
            g0.x = vr.x * c + vi.x * s;  g1.x = vi.x * c - vr.x * s;
            g0.y = vr.y * c + vi.y * s;  g1.y = vi.y * c - vr.y * s;
            g0.z = vr.z * c + vi.z * s;  g1.z = vi.z * c - vr.z * s;
            g0.w = vr.w * c + vi.w * s;  g1.w = vi.w * c - vr.w * s;
            *(float4*)&Gs[(2 * k) * 72 + cc * 4]     = totf32_4(g0);
            *(float4*)&Gs[(2 * k + 1) * 72 + cc * 4] = totf32_4(g1);
        }
#pragma unroll
        for (int i = 0; i < 4; i++) {                // pw rows 128..191: copy
            int idx = t + i * 256;
            int j = 128 + (idx >> 4), cc = idx & 15;
            *(float4*)&Gs[j * 72 + cc * 4] = totf32_4(src[j * 16 + cc]);
        }
        const float4* xs = (const float4*)(x + ((size_t)b * Ln + lt * 128) * Cn);
#pragma unroll
        for (int i = 0; i < 8; i++) {                // stage x: 2048 float4
            int idx = t + i * 256;
            int r = idx >> 4, cc = idx & 15;
            *(float4*)&As[r * 76 + cc * 4] = totf32_4(xs[idx]);
        }
    }
    __syncthreads();

    float c[2][4][4];
#pragma unroll
    for (int mt = 0; mt < 2; mt++)
#pragma unroll
        for (int nt = 0; nt < 4; nt++)
#pragma unroll
            for (int q = 0; q < 4; q++) c[mt][nt][q] = 0.0f;

    const float4* ap0 = (const float4*)g_b3frag + ((size_t)(2 * wm * 16) * 32 + lane);
    const float4* ap1 = ap0 + 16 * 32;
#pragma unroll
    for (int ks = 0; ks < 16; ks++) {                // basis part (K 0..127)
        float4 af0 = ap0[ks * 32];
        float4 af1 = ap1[ks * 32];
        uint32_t a0[4] = { fau(af0.x), fau(af0.y), fau(af0.z), fau(af0.w) };
        uint32_t a1[4] = { fau(af1.x), fau(af1.y), fau(af1.z), fau(af1.w) };
        int kr0 = ks * 8 + tg;
#pragma unroll
        for (int nt = 0; nt < 4; nt++) {
            int col = wn * 32 + nt * 8 + g;
            uint32_t b0 = fau(Gs[kr0 * 72 + col]);
            uint32_t b1 = fau(Gs[(kr0 + 4) * 72 + col]);
            mma_t32(c[0][nt], a0, b0, b1);
            mma_t32(c[1][nt], a1, b0, b1);
        }
    }
#pragma unroll
    for (int ks = 0; ks < 8; ks++) {                 // x part (K 128..191)
        int kk = ks * 8 + tg;
        int r0 = wm * 32 + g;
        uint32_t a0[4], a1[4];
        a0[0] = fau(As[r0 * 76 + kk]);
        a0[1] = fau(As[(r0 + 8) * 76 + kk]);
        a0[2] = fau(As[r0 * 76 + kk + 4]);
        a0[3] = fau(As[(r0 + 8) * 76 + kk + 4]);
        a1[0] = fau(As[(r0 + 16) * 76 + kk]);
        a1[1] = fau(As[(r0 + 24) * 76 + kk]);
        a1[2] = fau(As[(r0 + 16) * 76 + kk + 4]);
        a1[3] = fau(As[(r0 + 24) * 76 + kk + 4]);
        int kr0 = 128 + ks * 8 + tg;
#pragma unroll
        for (int nt = 0; nt < 4; nt++) {
            int col = wn * 32 + nt * 8 + g;
            uint32_t b0 = fau(Gs[kr0 * 72 + col]);
            uint32_t b1 = fau(Gs[(kr0 + 4) * 72 + col]);
            mma_t32(c[0][nt], a0, b0, b1);
            mma_t32(c[1][nt], a1, b0, b1);
        }
    }

#pragma unroll
    for (int mt = 0; mt < 2; mt++) {
        int l0 = lt * 128 + wm * 32 + mt * 16 + g;
        float* dst = out + ((size_t)b * Ln + l0) * Cn;
#pragma unroll
        for (int nt = 0; nt < 4; nt++) {
            int col = wn * 32 + nt * 8 + 2 * tg;
            float2 bb = *(const float2*)&bias[col];
            *(float2*)&dst[col] =
                make_float2(c[mt][nt][0] + bb.x, c[mt][nt][1] + bb.y);
            *(float2*)&dst[8 * Cn + col] =
                make_float2(c[mt][nt][2] + bb.x, c[mt][nt][3] + bb.y);
        }
    }
}

// ---------------------------------------------------------------------------
extern "C" void kernel_launch(void* const* d_in, const int* in_sizes, int n_in,
                              void* d_out, int out_size) {
    const float* x    = (const float*)d_in[0];
    const float* wr   = (const float*)d_in[1];
    const float* wi   = (const float*)d_in[2];
    const float* pw   = (const float*)d_in[3];
    const float* bias = (const float*)d_in[4];
    float* out = (float*)d_out;

    int smem3 = (192 * 72 + 128 * 76) * (int)sizeof(float);   // 94208 B -> 2 CTAs/SM
    cudaFuncSetAttribute(k_out, cudaFuncAttributeMaxDynamicSharedMemorySize, smem3);

    k_prep<<<608, 256>>>(wr, wi, pw);
    k_dft<<<dim3(NCH, Bn), 256>>>(x);
    k_mix<<<dim3(Mn, Bn), Cn>>>();
    k_out<<<dim3(Ln / 128, Bn), 256, smem3>>>(x, bias, out);
}

// round 15
// speedup vs baseline: 1.2510x; 1.2510x over previous
#include <cuda_runtime.h>
#include <cuda_fp16.h>
#include <math.h>
#include <stdint.h>

#define Bn 32
#define Ln 8192
#define Cn 64
#define Mn 64
#define Jn 128          // 2*Mn (cos/sin rows)
#define JG 192          // Jn + Cn
#define NCH 16          // stage-1 K chunks (K=512 each) -> 512 CTAs, single wave
#define TWOPI_8192 0.00076699039394282058f
#define SH 72           // smem row stride in halves (144B -> ldmatrix conflict-free)

// ---- scratch (device globals; no allocation allowed) ----
__device__ uint4 g_b1frag[8 * 512 * 32];        // stage-1 A frags [mt][ks16][lane] (2MB)
__device__ uint4 g_b3frag[64 * 8 * 8 * 32];     // stage-3 A frags [lt][mt][ks16][lane] (2MB)
__device__ float g_Aw[Mn * Cn * Cn];            // [k][i][o] = alpha_k * Wr
__device__ float g_Bw[Mn * Cn * Cn];            // [k][i][o] = alpha_k * Wi
__device__ float g_Pp[NCH * Bn * Jn * Cn];      // stage-1 partials [ch][b][j][c] fp32
__device__ float g_G[Bn * JG * Cn];             // stage-3 B operand [b][j][o] fp32

// ---------------- helpers ----------------
__device__ __forceinline__ uint32_t s2u(const void* p) {
    uint32_t a;
    asm("{ .reg .u64 t; cvta.to.shared.u64 t, %1; cvt.u32.u64 %0, t; }" : "=r"(a) : "l"(p));
    return a;
}
__device__ __forceinline__ uint32_t f2h2(float a, float b) {
    __half2 h = __floats2half2_rn(a, b);
    return *(uint32_t*)&h;
}
// float4 -> 4 halves packed as uint2
__device__ __forceinline__ uint2 f4h4(float4 v) {
    return make_uint2(f2h2(v.x, v.y), f2h2(v.z, v.w));
}

// fp16 m16n8k16 mma, fp32 accum
__device__ __forceinline__ void mma16(float c[4], const uint32_t a[4],
                                      uint32_t b0, uint32_t b1) {
    asm volatile(
        "mma.sync.aligned.m16n8k16.row.col.f32.f16.f16.f32 "
        "{%0,%1,%2,%3}, {%4,%5,%6,%7}, {%8,%9}, {%0,%1,%2,%3};"
        : "+f"(c[0]), "+f"(c[1]), "+f"(c[2]), "+f"(c[3])
        : "r"(a[0]), "r"(a[1]), "r"(a[2]), "r"(a[3]), "r"(b0), "r"(b1));
}

// ldmatrix x4 transposed (B operand from row-major [k][col] fp16 smem)
__device__ __forceinline__ void ldmat4t(uint32_t r[4], uint32_t addr) {
    asm volatile(
        "ldmatrix.sync.aligned.m8n8.x4.trans.shared.b16 {%0,%1,%2,%3}, [%4];"
        : "=r"(r[0]), "=r"(r[1]), "=r"(r[2]), "=r"(r[3]) : "r"(addr));
}

__device__ __forceinline__ float bval(int j, int l) {
    int m = ((j >> 1) * l) & (Ln - 1);           // exact: < 2^19
    float th = (float)m * TWOPI_8192;
    float s, c; __sincosf(th, &s, &c);
    return (j & 1) ? s : c;
}

// ---------------------------------------------------------------------------
// Merged prep: [0,512) stage-1 frags; [512,1024) stage-3 frags;
// [1024,1280) prepW; [1280,1312) pwfill.
// A fragment (m16k16 row-major): a0=(row g, k 2tg..2tg+1), a1=row+8,
// a2=k+8, a3=row+8,k+8.
// ---------------------------------------------------------------------------
__global__ void __launch_bounds__(256) k_prep(const float* __restrict__ wr,
                                              const float* __restrict__ wi,
                                              const float* __restrict__ pw) {
    __shared__ float t0[32][33], t1[32][33];
    int bx = blockIdx.x;
    if (bx < 512) {
        int g = bx * 256 + threadIdx.x;          // 131072
        int lane = g & 31, ks = (g >> 5) & 511, mt = g >> 14;
        int gid = lane >> 2, tg = lane & 3;
        int j = mt * 16 + gid, k0 = ks * 16 + 2 * tg;
        uint4 v;
        v.x = f2h2(bval(j, k0),         bval(j, k0 + 1));
        v.y = f2h2(bval(j + 8, k0),     bval(j + 8, k0 + 1));
        v.z = f2h2(bval(j, k0 + 8),     bval(j, k0 + 9));
        v.w = f2h2(bval(j + 8, k0 + 8), bval(j + 8, k0 + 9));
        g_b1frag[g] = v;
    } else if (bx < 1024) {
        int g = (bx - 512) * 256 + threadIdx.x;  // 131072
        int lane = g & 31, ks = (g >> 5) & 7, mt = (g >> 8) & 7, lt = g >> 11;
        int gid = lane >> 2, tg = lane & 3;
        int r = lt * 128 + mt * 16 + gid, j0 = ks * 16 + 2 * tg;
        // basisR[r][j] = bval(j, r)
        uint4 v;
        v.x = f2h2(bval(j0, r),         bval(j0 + 1, r));
        v.y = f2h2(bval(j0, r + 8),     bval(j0 + 1, r + 8));
        v.z = f2h2(bval(j0 + 8, r),     bval(j0 + 9, r));
        v.w = f2h2(bval(j0 + 8, r + 8), bval(j0 + 9, r + 8));
        g_b3frag[g] = v;
    } else if (bx < 1280) {
        int tile = bx - 1024;
        int rc0 = (tile >> 1) * 32, k0 = (tile & 1) * 32;
        int tx = threadIdx.x & 31, ty = threadIdx.x >> 5;
#pragma unroll
        for (int rr = ty; rr < 32; rr += 8) {
            t0[rr][tx] = wr[(rc0 + rr) * 64 + k0 + tx];
            t1[rr][tx] = wi[(rc0 + rr) * 64 + k0 + tx];
        }
        __syncthreads();
#pragma unroll
        for (int kk = ty; kk < 32; kk += 8) {
            int k = k0 + kk;
            float alpha = (k == 0 ? 1.0f : 2.0f) / (float)Ln;
            g_Aw[k * 4096 + rc0 + tx] = alpha * t0[tx][kk];
            g_Bw[k * 4096 + rc0 + tx] = alpha * t1[tx][kk];
        }
    } else {
        int b = bx - 1280, t = threadIdx.x;
#pragma unroll
        for (int i = 0; i < 16; i++) {
            int idx = t + i * 256;
            int o = idx & 63, ic = idx >> 6;
            g_G[(b * JG + Jn + ic) * Cn + o] = pw[o * Cn + ic];
        }
    }
}

// ---------------------------------------------------------------------------
// Stage 1: P[j=128][c=64] = sum_l basis[j,l]*x[l,c]; K=512 per block, fp16 MMA.
// 8 warps; warp w = m-tile (16 j rows).  Double-buffered fp16 x staging.
// ---------------------------------------------------------------------------
__global__ void __launch_bounds__(256) k_dft(const float* __restrict__ x) {
    int ch = blockIdx.x, b = blockIdx.y;
    __shared__ __align__(16) __half Xs[2][32 * SH];
    int t = threadIdx.x, w = t >> 5, lane = t & 31;
    int gid = lane >> 2, tg = lane & 3;
    int row0 = t >> 4, c4 = t & 15;
    uint32_t xs0 = s2u(Xs);
    uint32_t laneB = ((((lane >> 3) & 1) * 8 + (lane & 7)) * SH + ((lane >> 4) & 1) * 8) * 2;

    float c[8][4];
#pragma unroll
    for (int nt = 0; nt < 8; nt++)
#pragma unroll
        for (int q = 0; q < 4; q++) c[nt][q] = 0.0f;

    const uint4* ap = g_b1frag + ((size_t)(w * 512 + ch * 32)) * 32 + lane;
    const float* xb = x + (size_t)b * Ln * Cn + (size_t)ch * 512 * Cn;

    {   // stage tile 0
        float4 v0 = *(const float4*)&xb[row0 * Cn + c4 * 4];
        float4 v1 = *(const float4*)&xb[(row0 + 16) * Cn + c4 * 4];
        *(uint2*)&Xs[0][row0 * SH + c4 * 4] = f4h4(v0);
        *(uint2*)&Xs[0][(row0 + 16) * SH + c4 * 4] = f4h4(v1);
    }
    __syncthreads();

    for (int kc = 0; kc < 16; kc++) {
        int cur = kc & 1;
        float4 n0, n1;
        if (kc < 15) {                           // prefetch next tile
            const float* xn = xb + (kc + 1) * 32 * Cn;
            n0 = *(const float4*)&xn[row0 * Cn + c4 * 4];
            n1 = *(const float4*)&xn[(row0 + 16) * Cn + c4 * 4];
        }
        uint4 af[2];
        af[0] = ap[(kc * 2) * 32];
        af[1] = ap[(kc * 2 + 1) * 32];
        uint32_t bufB = xs0 + cur * (32 * SH * 2) + laneB;
#pragma unroll
        for (int s = 0; s < 2; s++) {
            uint32_t a[4] = { af[s].x, af[s].y, af[s].z, af[s].w };
            uint32_t stepB = bufB + s * (16 * SH * 2);
#pragma unroll
            for (int p = 0; p < 4; p++) {
                uint32_t br[4];
                ldmat4t(br, stepB + p * 32);
                mma16(c[2 * p], a, br[0], br[1]);
                mma16(c[2 * p + 1], a, br[2], br[3]);
            }
        }
        if (kc < 15) {
            *(uint2*)&Xs[cur ^ 1][row0 * SH + c4 * 4] = f4h4(n0);
            *(uint2*)&Xs[cur ^ 1][(row0 + 16) * SH + c4 * 4] = f4h4(n1);
        }
        __syncthreads();
    }

    float* dst = g_Pp + ((size_t)(ch * Bn + b) * Jn) * Cn;
    int j0 = w * 16 + gid;
#pragma unroll
    for (int nt = 0; nt < 8; nt++) {
        *(float2*)&dst[j0 * Cn + nt * 8 + 2 * tg]       = make_float2(c[nt][0], c[nt][1]);
        *(float2*)&dst[(j0 + 8) * Cn + nt * 8 + 2 * tg] = make_float2(c[nt][2], c[nt][3]);
    }
}

// ---------------------------------------------------------------------------
// Stage 2: fused partial-reduce + complex mix (fp32, unchanged).
// ---------------------------------------------------------------------------
__global__ void k_mix() {
    int k = blockIdx.x, b = blockIdx.y, o = threadIdx.x;
    __shared__ float P0[Cn], P1[Cn];
    float p0 = 0.0f, p1 = 0.0f;
#pragma unroll 4
    for (int ch = 0; ch < NCH; ch++) {
        const float* src = g_Pp + ((size_t)(ch * Bn + b) * Jn + 2 * k) * Cn;
        p0 += src[o];
        p1 += src[Cn + o];
    }
    P0[o] = p0; P1[o] = p1;
    __syncthreads();
    float gr = 0.0f, gi = 0.0f;
#pragma unroll 8
    for (int i = 0; i < Cn; i++) {
        float a  = g_Aw[(k * Cn + i) * Cn + o];
        float bb = g_Bw[(k * Cn + i) * Cn + o];
        float pr = P0[i], pi = P1[i];
        gr += pr * a + pi * bb;
        gi += pi * a - pr * bb;
    }
    g_G[(b * JG + 2 * k) * Cn + o]     = gr;
    g_G[(b * JG + 2 * k + 1) * Cn + o] = gi;
}

// ---------------------------------------------------------------------------
// Stage 3: out[l=128][o=64] = sum_{j<192} bigA[l,j]*G[j,o] + bias; fp16 MMA.
// smem fp16: Gs 27.6KB + As 18.4KB = 46KB -> 4 CTAs/SM.
// ---------------------------------------------------------------------------
__global__ void __launch_bounds__(256) k_out(const float* __restrict__ x,
                                             const float* __restrict__ bias,
                                             float* __restrict__ out) {
    int lt = blockIdx.x, b = blockIdx.y;
    __shared__ __align__(16) __half Gs[JG * SH];
    __shared__ __align__(16) __half As[128 * SH];
    int t = threadIdx.x, w = t >> 5, lane = t & 31;
    int gid = lane >> 2, tg = lane & 3;
    uint32_t gs0 = s2u(Gs);
    uint32_t laneB = ((((lane >> 3) & 1) * 8 + (lane & 7)) * SH + ((lane >> 4) & 1) * 8) * 2;

    {   // stage G (fp32 -> fp16): 3072 float4
        const float4* src = (const float4*)(g_G + (size_t)b * JG * Cn);
#pragma unroll
        for (int i = 0; i < 12; i++) {
            int idx = t + i * 256;
            int j = idx >> 4, cc = idx & 15;
            *(uint2*)&Gs[j * SH + cc * 4] = f4h4(src[idx]);
        }
        const float4* xs = (const float4*)(x + ((size_t)b * Ln + lt * 128) * Cn);
#pragma unroll
        for (int i = 0; i < 8; i++) {            // stage x: 2048 float4
            int idx = t + i * 256;
            int r = idx >> 4, cc = idx & 15;
            *(uint2*)&As[r * SH + cc * 4] = f4h4(xs[idx]);
        }
    }
    __syncthreads();

    float c[8][4];
#pragma unroll
    for (int nt = 0; nt < 8; nt++)
#pragma unroll
        for (int q = 0; q < 4; q++) c[nt][q] = 0.0f;

    const uint4* ap = g_b3frag + ((size_t)(lt * 8 + w)) * 8 * 32 + lane;
#pragma unroll
    for (int ks = 0; ks < 8; ks++) {             // basis part (K 0..127)
        uint4 af = ap[ks * 32];
        uint32_t a[4] = { af.x, af.y, af.z, af.w };
        uint32_t stepB = gs0 + laneB + ks * (16 * SH * 2);
#pragma unroll
        for (int p = 0; p < 4; p++) {
            uint32_t br[4];
            ldmat4t(br, stepB + p * 32);
            mma16(c[2 * p], a, br[0], br[1]);
            mma16(c[2 * p + 1], a, br[2], br[3]);
        }
    }
#pragma unroll
    for (int ks = 0; ks < 4; ks++) {             // x part (K 128..191)
        int r0 = w * 16 + gid, kk = ks * 16 + 2 * tg;
        uint32_t a[4];
        a[0] = *(const uint32_t*)&As[r0 * SH + kk];
        a[1] = *(const uint32_t*)&As[(r0 + 8) * SH + kk];
        a[2] = *(const uint32_t*)&As[r0 * SH + kk + 8];
        a[3] = *(const uint32_t*)&As[(r0 + 8) * SH + kk + 8];
        uint32_t stepB = gs0 + laneB + (128 + ks * 16) * (SH * 2);
#pragma unroll
        for (int p = 0; p < 4; p++) {
            uint32_t br[4];
            ldmat4t(br, stepB + p * 32);
            mma16(c[2 * p], a, br[0], br[1]);
            mma16(c[2 * p + 1], a, br[2], br[3]);
        }
    }

    int l0 = lt * 128 + w * 16 + gid;
#pragma unroll
    for (int nt = 0; nt < 8; nt++) {
        int col = nt * 8 + 2 * tg;
        float2 bb = *(const float2*)&bias[col];
        *(float2*)&out[((size_t)b * Ln + l0) * Cn + col] =
            make_float2(c[nt][0] + bb.x, c[nt][1] + bb.y);
        *(float2*)&out[((size_t)b * Ln + l0 + 8) * Cn + col] =
            make_float2(c[nt][2] + bb.x, c[nt][3] + bb.y);
    }
}

// ---------------------------------------------------------------------------
extern "C" void kernel_launch(void* const* d_in, const int* in_sizes, int n_in,
                              void* d_out, int out_size) {
    const float* x    = (const float*)d_in[0];
    const float* wr   = (const float*)d_in[1];
    const float* wi   = (const float*)d_in[2];
    const float* pw   = (const float*)d_in[3];
    const float* bias = (const float*)d_in[4];
    float* out = (float*)d_out;

    k_prep<<<1312, 256>>>(wr, wi, pw);
    k_dft<<<dim3(NCH, Bn), 256>>>(x);
    k_mix<<<dim3(Mn, Bn), Cn>>>();
    k_out<<<dim3(Ln / 128, Bn), 256>>>(x, bias, out);
}

// round 16
// speedup vs baseline: 1.3996x; 1.1188x over previous
#include <cuda_runtime.h>
#include <cuda_fp16.h>
#include <math.h>
#include <stdint.h>

#define Bn 32
#define Ln 8192
#define Cn 64
#define Mn 64
#define Jn 128          // 2*Mn (cos/sin rows)
#define JG 192          // Jn + Cn
#define NCH 16          // stage-1 K chunks (K=512 each) -> 512 CTAs
#define TWOPI_8192 0.00076699039394282058f
#define SH 72           // smem row stride in halves (144B -> ldmatrix conflict-free)

// ---- scratch (device globals; no allocation allowed) ----
__device__ uint4 g_b1frag[8 * 512 * 32];        // stage-1 A frags [mt][ks16][lane] (2MB)
__device__ uint4 g_b3frag[64 * 8 * 8 * 32];     // stage-3 A frags [lt][mt][ks16][lane] (2MB)
__device__ float g_Aw[Mn * Cn * Cn];            // [k][i][o] = alpha_k * Wr
__device__ float g_Bw[Mn * Cn * Cn];            // [k][i][o] = alpha_k * Wi
__device__ __half g_Pp[NCH * Bn * Jn * Cn];     // stage-1 partials [ch][b][j][c] fp16 (8.4MB)
__device__ float g_G[Bn * JG * Cn];             // stage-3 B operand [b][j][o] fp32

// ---------------- helpers ----------------
__device__ __forceinline__ uint32_t s2u(const void* p) {
    uint32_t a;
    asm("{ .reg .u64 t; cvta.to.shared.u64 t, %1; cvt.u32.u64 %0, t; }" : "=r"(a) : "l"(p));
    return a;
}
__device__ __forceinline__ uint32_t f2h2(float a, float b) {
    __half2 h = __floats2half2_rn(a, b);
    return *(uint32_t*)&h;
}
__device__ __forceinline__ uint2 f4h4(float4 v) {
    return make_uint2(f2h2(v.x, v.y), f2h2(v.z, v.w));
}

// fp16 m16n8k16 mma, fp32 accum
__device__ __forceinline__ void mma16(float c[4], const uint32_t a[4],
                                      uint32_t b0, uint32_t b1) {
    asm volatile(
        "mma.sync.aligned.m16n8k16.row.col.f32.f16.f16.f32 "
        "{%0,%1,%2,%3}, {%4,%5,%6,%7}, {%8,%9}, {%0,%1,%2,%3};"
        : "+f"(c[0]), "+f"(c[1]), "+f"(c[2]), "+f"(c[3])
        : "r"(a[0]), "r"(a[1]), "r"(a[2]), "r"(a[3]), "r"(b0), "r"(b1));
}

// ldmatrix x4 transposed
__device__ __forceinline__ void ldmat4t(uint32_t r[4], uint32_t addr) {
    asm volatile(
        "ldmatrix.sync.aligned.m8n8.x4.trans.shared.b16 {%0,%1,%2,%3}, [%4];"
        : "=r"(r[0]), "=r"(r[1]), "=r"(r[2]), "=r"(r[3]) : "r"(addr));
}

__device__ __forceinline__ float bval(int j, int l) {
    int m = ((j >> 1) * l) & (Ln - 1);           // exact: < 2^19
    float th = (float)m * TWOPI_8192;
    float s, c; __sincosf(th, &s, &c);
    return (j & 1) ? s : c;
}

// ---------------------------------------------------------------------------
// Merged prep: [0,512) stage-1 frags; [512,1024) stage-3 frags;
// [1024,1280) prepW; [1280,1312) pwfill.
// ---------------------------------------------------------------------------
__global__ void __launch_bounds__(256) k_prep(const float* __restrict__ wr,
                                              const float* __restrict__ wi,
                                              const float* __restrict__ pw) {
    __shared__ float t0[32][33], t1[32][33];
    int bx = blockIdx.x;
    if (bx < 512) {
        int g = bx * 256 + threadIdx.x;          // 131072
        int lane = g & 31, ks = (g >> 5) & 511, mt = g >> 14;
        int gid = lane >> 2, tg = lane & 3;
        int j = mt * 16 + gid, k0 = ks * 16 + 2 * tg;
        uint4 v;
        v.x = f2h2(bval(j, k0),         bval(j, k0 + 1));
        v.y = f2h2(bval(j + 8, k0),     bval(j + 8, k0 + 1));
        v.z = f2h2(bval(j, k0 + 8),     bval(j, k0 + 9));
        v.w = f2h2(bval(j + 8, k0 + 8), bval(j + 8, k0 + 9));
        g_b1frag[g] = v;
    } else if (bx < 1024) {
        int g = (bx - 512) * 256 + threadIdx.x;  // 131072
        int lane = g & 31, ks = (g >> 5) & 7, mt = (g >> 8) & 7, lt = g >> 11;
        int gid = lane >> 2, tg = lane & 3;
        int r = lt * 128 + mt * 16 + gid, j0 = ks * 16 + 2 * tg;
        uint4 v;
        v.x = f2h2(bval(j0, r),         bval(j0 + 1, r));
        v.y = f2h2(bval(j0, r + 8),     bval(j0 + 1, r + 8));
        v.z = f2h2(bval(j0 + 8, r),     bval(j0 + 9, r));
        v.w = f2h2(bval(j0 + 8, r + 8), bval(j0 + 9, r + 8));
        g_b3frag[g] = v;
    } else if (bx < 1280) {
        int tile = bx - 1024;
        int rc0 = (tile >> 1) * 32, k0 = (tile & 1) * 32;
        int tx = threadIdx.x & 31, ty = threadIdx.x >> 5;
#pragma unroll
        for (int rr = ty; rr < 32; rr += 8) {
            t0[rr][tx] = wr[(rc0 + rr) * 64 + k0 + tx];
            t1[rr][tx] = wi[(rc0 + rr) * 64 + k0 + tx];
        }
        __syncthreads();
#pragma unroll
        for (int kk = ty; kk < 32; kk += 8) {
            int k = k0 + kk;
            float alpha = (k == 0 ? 1.0f : 2.0f) / (float)Ln;
            g_Aw[k * 4096 + rc0 + tx] = alpha * t0[tx][kk];
            g_Bw[k * 4096 + rc0 + tx] = alpha * t1[tx][kk];
        }
    } else {
        int b = bx - 1280, t = threadIdx.x;
#pragma unroll
        for (int i = 0; i < 16; i++) {
            int idx = t + i * 256;
            int o = idx & 63, ic = idx >> 6;
            g_G[(b * JG + Jn + ic) * Cn + o] = pw[o * Cn + ic];
        }
    }
}

// ---------------------------------------------------------------------------
// Stage 1: P[j=128][c=64] = sum_l basis[j,l]*x[l,c]; K=512 per block, fp16 MMA.
// ---------------------------------------------------------------------------
__global__ void __launch_bounds__(256, 4) k_dft(const float* __restrict__ x) {
    int ch = blockIdx.x, b = blockIdx.y;
    __shared__ __align__(16) __half Xs[2][32 * SH];
    int t = threadIdx.x, w = t >> 5, lane = t & 31;
    int gid = lane >> 2, tg = lane & 3;
    int row0 = t >> 4, c4 = t & 15;
    uint32_t xs0 = s2u(Xs);
    uint32_t laneB = ((((lane >> 3) & 1) * 8 + (lane & 7)) * SH + ((lane >> 4) & 1) * 8) * 2;

    float c[8][4];
#pragma unroll
    for (int nt = 0; nt < 8; nt++)
#pragma unroll
        for (int q = 0; q < 4; q++) c[nt][q] = 0.0f;

    const uint4* ap = g_b1frag + ((size_t)(w * 512 + ch * 32)) * 32 + lane;
    const float* xb = x + (size_t)b * Ln * Cn + (size_t)ch * 512 * Cn;

    {   // stage tile 0
        float4 v0 = *(const float4*)&xb[row0 * Cn + c4 * 4];
        float4 v1 = *(const float4*)&xb[(row0 + 16) * Cn + c4 * 4];
        *(uint2*)&Xs[0][row0 * SH + c4 * 4] = f4h4(v0);
        *(uint2*)&Xs[0][(row0 + 16) * SH + c4 * 4] = f4h4(v1);
    }
    __syncthreads();

    for (int kc = 0; kc < 16; kc++) {
        int cur = kc & 1;
        float4 n0, n1;
        if (kc < 15) {                           // prefetch next tile
            const float* xn = xb + (kc + 1) * 32 * Cn;
            n0 = *(const float4*)&xn[row0 * Cn + c4 * 4];
            n1 = *(const float4*)&xn[(row0 + 16) * Cn + c4 * 4];
        }
        uint4 af[2];
        af[0] = ap[(kc * 2) * 32];
        af[1] = ap[(kc * 2 + 1) * 32];
        uint32_t bufB = xs0 + cur * (32 * SH * 2) + laneB;
#pragma unroll
        for (int s = 0; s < 2; s++) {
            uint32_t a[4] = { af[s].x, af[s].y, af[s].z, af[s].w };
            uint32_t stepB = bufB + s * (16 * SH * 2);
#pragma unroll
            for (int p = 0; p < 4; p++) {
                uint32_t br[4];
                ldmat4t(br, stepB + p * 32);
                mma16(c[2 * p], a, br[0], br[1]);
                mma16(c[2 * p + 1], a, br[2], br[3]);
            }
        }
        if (kc < 15) {
            *(uint2*)&Xs[cur ^ 1][row0 * SH + c4 * 4] = f4h4(n0);
            *(uint2*)&Xs[cur ^ 1][(row0 + 16) * SH + c4 * 4] = f4h4(n1);
        }
        __syncthreads();
    }

    // D store as fp16 pairs (4B per nt per row)
    __half* dst = g_Pp + ((size_t)(ch * Bn + b) * Jn) * Cn;
    int j0 = w * 16 + gid;
#pragma unroll
    for (int nt = 0; nt < 8; nt++) {
        *(uint32_t*)&dst[j0 * Cn + nt * 8 + 2 * tg]       = f2h2(c[nt][0], c[nt][1]);
        *(uint32_t*)&dst[(j0 + 8) * Cn + nt * 8 + 2 * tg] = f2h2(c[nt][2], c[nt][3]);
    }
}

// ---------------------------------------------------------------------------
// Stage 2: fused partial-reduce + complex mix.  256 thr = 4 modes x 64 o.
// ---------------------------------------------------------------------------
__global__ void __launch_bounds__(256) k_mix() {
    int kq = threadIdx.x >> 6, o = threadIdx.x & 63;
    int k = blockIdx.x * 4 + kq, b = blockIdx.y;
    __shared__ float P0[4][Cn], P1[4][Cn];
    float p0 = 0.0f, p1 = 0.0f;
#pragma unroll 4
    for (int ch = 0; ch < NCH; ch++) {
        const __half* src = g_Pp + ((size_t)(ch * Bn + b) * Jn + 2 * k) * Cn;
        p0 += __half2float(src[o]);
        p1 += __half2float(src[Cn + o]);
    }
    P0[kq][o] = p0; P1[kq][o] = p1;
    __syncthreads();
    float gr = 0.0f, gi = 0.0f;
#pragma unroll 8
    for (int i = 0; i < Cn; i++) {
        float a  = g_Aw[(k * Cn + i) * Cn + o];
        float bb = g_Bw[(k * Cn + i) * Cn + o];
        float pr = P0[kq][i], pi = P1[kq][i];
        gr += pr * a + pi * bb;
        gi += pi * a - pr * bb;
    }
    g_G[(b * JG + 2 * k) * Cn + o]     = gr;
    g_G[(b * JG + 2 * k + 1) * Cn + o] = gi;
}

// ---------------------------------------------------------------------------
// Stage 3: out[l=128][o=64] = sum_{j<192} bigA[l,j]*G[j,o] + bias; fp16 MMA.
// ---------------------------------------------------------------------------
__global__ void __launch_bounds__(256, 4) k_out(const float* __restrict__ x,
                                                const float* __restrict__ bias,
                                                float* __restrict__ out) {
    int lt = blockIdx.x, b = blockIdx.y;
    __shared__ __align__(16) __half Gs[JG * SH];
    __shared__ __align__(16) __half As[128 * SH];
    int t = threadIdx.x, w = t >> 5, lane = t & 31;
    int gid = lane >> 2, tg = lane & 3;
    uint32_t gs0 = s2u(Gs);
    uint32_t laneB = ((((lane >> 3) & 1) * 8 + (lane & 7)) * SH + ((lane >> 4) & 1) * 8) * 2;

    {   // stage G (fp32 -> fp16): 3072 float4
        const float4* src = (const float4*)(g_G + (size_t)b * JG * Cn);
#pragma unroll
        for (int i = 0; i < 12; i++) {
            int idx = t + i * 256;
            int j = idx >> 4, cc = idx & 15;
            *(uint2*)&Gs[j * SH + cc * 4] = f4h4(src[idx]);
        }
        const float4* xs = (const float4*)(x + ((size_t)b * Ln + lt * 128) * Cn);
#pragma unroll
        for (int i = 0; i < 8; i++) {            // stage x: 2048 float4
            int idx = t + i * 256;
            int r = idx >> 4, cc = idx & 15;
            *(uint2*)&As[r * SH + cc * 4] = f4h4(xs[idx]);
        }
    }
    __syncthreads();

    float c[8][4];
#pragma unroll
    for (int nt = 0; nt < 8; nt++)
#pragma unroll
        for (int q = 0; q < 4; q++) c[nt][q] = 0.0f;

    const uint4* ap = g_b3frag + ((size_t)(lt * 8 + w)) * 8 * 32 + lane;
#pragma unroll
    for (int ks = 0; ks < 8; ks++) {             // basis part (K 0..127)
        uint4 af = ap[ks * 32];
        uint32_t a[4] = { af.x, af.y, af.z, af.w };
        uint32_t stepB = gs0 + laneB + ks * (16 * SH * 2);
#pragma unroll
        for (int p = 0; p < 4; p++) {
            uint32_t br[4];
            ldmat4t(br, stepB + p * 32);
            mma16(c[2 * p], a, br[0], br[1]);
            mma16(c[2 * p + 1], a, br[2], br[3]);
        }
    }
#pragma unroll
    for (int ks = 0; ks < 4; ks++) {             // x part (K 128..191)
        int r0 = w * 16 + gid, kk = ks * 16 + 2 * tg;
        uint32_t a[4];
        a[0] = *(const uint32_t*)&As[r0 * SH + kk];
        a[1] = *(const uint32_t*)&As[(r0 + 8) * SH + kk];
        a[2] = *(const uint32_t*)&As[r0 * SH + kk + 8];
        a[3] = *(const uint32_t*)&As[(r0 + 8) * SH + kk + 8];
        uint32_t stepB = gs0 + laneB + (128 + ks * 16) * (SH * 2);
#pragma unroll
        for (int p = 0; p < 4; p++) {
            uint32_t br[4];
            ldmat4t(br, stepB + p * 32);
            mma16(c[2 * p], a, br[0], br[1]);
            mma16(c[2 * p + 1], a, br[2], br[3]);
        }
    }

    int l0 = lt * 128 + w * 16 + gid;
#pragma unroll
    for (int nt = 0; nt < 8; nt++) {
        int col = nt * 8 + 2 * tg;
        float2 bb = *(const float2*)&bias[col];
        *(float2*)&out[((size_t)b * Ln + l0) * Cn + col] =
            make_float2(c[nt][0] + bb.x, c[nt][1] + bb.y);
        *(float2*)&out[((size_t)b * Ln + l0 + 8) * Cn + col] =
            make_float2(c[nt][2] + bb.x, c[nt][3] + bb.y);
    }
}

// ---------------------------------------------------------------------------
extern "C" void kernel_launch(void* const* d_in, const int* in_sizes, int n_in,
                              void* d_out, int out_size) {
    const float* x    = (const float*)d_in[0];
    const float* wr   = (const float*)d_in[1];
    const float* wi   = (const float*)d_in[2];
    const float* pw   = (const float*)d_in[3];
    const float* bias = (const float*)d_in[4];
    float* out = (float*)d_out;

    k_prep<<<1312, 256>>>(wr, wi, pw);
    k_dft<<<dim3(NCH, Bn), 256>>>(x);
    k_mix<<<dim3(Mn / 4, Bn), 256>>>();
    k_out<<<dim3(Ln / 128, Bn), 256>>>(x, bias, out);
}

// round 17
// speedup vs baseline: 1.4468x; 1.0337x over previous
#include <cuda_runtime.h>
#include <cuda_fp16.h>
#include <math.h>
#include <stdint.h>

#define Bn 32
#define Ln 8192
#define Cn 64
#define Mn 64
#define Jn 128          // 2*Mn (cos/sin rows)
#define JG 192          // Jn + Cn
#define NCH 16          // stage-1 K chunks (K=512 each) -> 512 CTAs
#define TWOPI_8192 0.00076699039394282058f
#define SH 72           // smem row stride in halves (144B -> ldmatrix conflict-free)

// ---- scratch (device globals; no allocation allowed) ----
__device__ uint4 g_b1frag[8 * 512 * 32];        // stage-1 A frags [mt][ks16][lane] (2MB)
__device__ uint4 g_b3frag[64 * 8 * 8 * 32];     // stage-3 A frags [lt][mt][ks16][lane] (2MB)
__device__ float g_Aw[Mn * Cn * Cn];            // [k][i][o] = alpha_k * Wr
__device__ float g_Bw[Mn * Cn * Cn];            // [k][i][o] = alpha_k * Wi
__device__ __half g_Pp[NCH * Bn * Jn * Cn];     // stage-1 partials [ch][b][j][c] fp16
__device__ float g_G[Bn * JG * Cn];             // stage-3 B operand [b][j][o] fp32

// ---------------- helpers ----------------
__device__ __forceinline__ uint32_t s2u(const void* p) {
    uint32_t a;
    asm("{ .reg .u64 t; cvta.to.shared.u64 t, %1; cvt.u32.u64 %0, t; }" : "=r"(a) : "l"(p));
    return a;
}
__device__ __forceinline__ uint32_t f2h2(float a, float b) {
    __half2 h = __floats2half2_rn(a, b);
    return *(uint32_t*)&h;
}
__device__ __forceinline__ uint2 f4h4(float4 v) {
    return make_uint2(f2h2(v.x, v.y), f2h2(v.z, v.w));
}

// fp16 m16n8k16 mma, fp32 accum
__device__ __forceinline__ void mma16(float c[4], const uint32_t a[4],
                                      uint32_t b0, uint32_t b1) {
    asm volatile(
        "mma.sync.aligned.m16n8k16.row.col.f32.f16.f16.f32 "
        "{%0,%1,%2,%3}, {%4,%5,%6,%7}, {%8,%9}, {%0,%1,%2,%3};"
        : "+f"(c[0]), "+f"(c[1]), "+f"(c[2]), "+f"(c[3])
        : "r"(a[0]), "r"(a[1]), "r"(a[2]), "r"(a[3]), "r"(b0), "r"(b1));
}

// ldmatrix x4 transposed
__device__ __forceinline__ void ldmat4t(uint32_t r[4], uint32_t addr) {
    asm volatile(
        "ldmatrix.sync.aligned.m8n8.x4.trans.shared.b16 {%0,%1,%2,%3}, [%4];"
        : "=r"(r[0]), "=r"(r[1]), "=r"(r[2]), "=r"(r[3]) : "r"(addr));
}

__device__ __forceinline__ float bval(int j, int l) {
    int m = ((j >> 1) * l) & (Ln - 1);           // exact: < 2^19
    float th = (float)m * TWOPI_8192;
    float s, c; __sincosf(th, &s, &c);
    return (j & 1) ? s : c;
}

// ---------------------------------------------------------------------------
// Merged prep: [0,512) stage-1 frags; [512,1024) stage-3 frags;
// [1024,1280) prepW; [1280,1312) pwfill.
// ---------------------------------------------------------------------------
__global__ void __launch_bounds__(256) k_prep(const float* __restrict__ wr,
                                              const float* __restrict__ wi,
                                              const float* __restrict__ pw) {
    __shared__ float t0[32][33], t1[32][33];
    int bx = blockIdx.x;
    if (bx < 512) {
        int g = bx * 256 + threadIdx.x;          // 131072
        int lane = g & 31, ks = (g >> 5) & 511, mt = g >> 14;
        int gid = lane >> 2, tg = lane & 3;
        int j = mt * 16 + gid, k0 = ks * 16 + 2 * tg;
        uint4 v;
        v.x = f2h2(bval(j, k0),         bval(j, k0 + 1));
        v.y = f2h2(bval(j + 8, k0),     bval(j + 8, k0 + 1));
        v.z = f2h2(bval(j, k0 + 8),     bval(j, k0 + 9));
        v.w = f2h2(bval(j + 8, k0 + 8), bval(j + 8, k0 + 9));
        g_b1frag[g] = v;
    } else if (bx < 1024) {
        int g = (bx - 512) * 256 + threadIdx.x;  // 131072
        int lane = g & 31, ks = (g >> 5) & 7, mt = (g >> 8) & 7, lt = g >> 11;
        int gid = lane >> 2, tg = lane & 3;
        int r = lt * 128 + mt * 16 + gid, j0 = ks * 16 + 2 * tg;
        uint4 v;
        v.x = f2h2(bval(j0, r),         bval(j0 + 1, r));
        v.y = f2h2(bval(j0, r + 8),     bval(j0 + 1, r + 8));
        v.z = f2h2(bval(j0 + 8, r),     bval(j0 + 9, r));
        v.w = f2h2(bval(j0 + 8, r + 8), bval(j0 + 9, r + 8));
        g_b3frag[g] = v;
    } else if (bx < 1280) {
        int tile = bx - 1024;
        int rc0 = (tile >> 1) * 32, k0 = (tile & 1) * 32;
        int tx = threadIdx.x & 31, ty = threadIdx.x >> 5;
#pragma unroll
        for (int rr = ty; rr < 32; rr += 8) {
            t0[rr][tx] = wr[(rc0 + rr) * 64 + k0 + tx];
            t1[rr][tx] = wi[(rc0 + rr) * 64 + k0 + tx];
        }
        __syncthreads();
#pragma unroll
        for (int kk = ty; kk < 32; kk += 8) {
            int k = k0 + kk;
            float alpha = (k == 0 ? 1.0f : 2.0f) / (float)Ln;
            g_Aw[k * 4096 + rc0 + tx] = alpha * t0[tx][kk];
            g_Bw[k * 4096 + rc0 + tx] = alpha * t1[tx][kk];
        }
    } else {
        int b = bx - 1280, t = threadIdx.x;
#pragma unroll
        for (int i = 0; i < 16; i++) {
            int idx = t + i * 256;
            int o = idx & 63, ic = idx >> 6;
            g_G[(b * JG + Jn + ic) * Cn + o] = pw[o * Cn + ic];
        }
    }
}

// ---------------------------------------------------------------------------
// Stage 1: P[j=128][c=64] = sum_l basis[j,l]*x[l,c]; K=512 per block, fp16 MMA.
// (R16 version, unchanged.)
// ---------------------------------------------------------------------------
__global__ void __launch_bounds__(256, 4) k_dft(const float* __restrict__ x) {
    int ch = blockIdx.x, b = blockIdx.y;
    __shared__ __align__(16) __half Xs[2][32 * SH];
    int t = threadIdx.x, w = t >> 5, lane = t & 31;
    int gid = lane >> 2, tg = lane & 3;
    int row0 = t >> 4, c4 = t & 15;
    uint32_t xs0 = s2u(Xs);
    uint32_t laneB = ((((lane >> 3) & 1) * 8 + (lane & 7)) * SH + ((lane >> 4) & 1) * 8) * 2;

    float c[8][4];
#pragma unroll
    for (int nt = 0; nt < 8; nt++)
#pragma unroll
        for (int q = 0; q < 4; q++) c[nt][q] = 0.0f;

    const uint4* ap = g_b1frag + ((size_t)(w * 512 + ch * 32)) * 32 + lane;
    const float* xb = x + (size_t)b * Ln * Cn + (size_t)ch * 512 * Cn;

    {   // stage tile 0
        float4 v0 = *(const float4*)&xb[row0 * Cn + c4 * 4];
        float4 v1 = *(const float4*)&xb[(row0 + 16) * Cn + c4 * 4];
        *(uint2*)&Xs[0][row0 * SH + c4 * 4] = f4h4(v0);
        *(uint2*)&Xs[0][(row0 + 16) * SH + c4 * 4] = f4h4(v1);
    }
    __syncthreads();

    for (int kc = 0; kc < 16; kc++) {
        int cur = kc & 1;
        float4 n0, n1;
        if (kc < 15) {                           // prefetch next tile
            const float* xn = xb + (kc + 1) * 32 * Cn;
            n0 = *(const float4*)&xn[row0 * Cn + c4 * 4];
            n1 = *(const float4*)&xn[(row0 + 16) * Cn + c4 * 4];
        }
        uint4 af[2];
        af[0] = ap[(kc * 2) * 32];
        af[1] = ap[(kc * 2 + 1) * 32];
        uint32_t bufB = xs0 + cur * (32 * SH * 2) + laneB;
#pragma unroll
        for (int s = 0; s < 2; s++) {
            uint32_t a[4] = { af[s].x, af[s].y, af[s].z, af[s].w };
            uint32_t stepB = bufB + s * (16 * SH * 2);
#pragma unroll
            for (int p = 0; p < 4; p++) {
                uint32_t br[4];
                ldmat4t(br, stepB + p * 32);
                mma16(c[2 * p], a, br[0], br[1]);
                mma16(c[2 * p + 1], a, br[2], br[3]);
            }
        }
        if (kc < 15) {
            *(uint2*)&Xs[cur ^ 1][row0 * SH + c4 * 4] = f4h4(n0);
            *(uint2*)&Xs[cur ^ 1][(row0 + 16) * SH + c4 * 4] = f4h4(n1);
        }
        __syncthreads();
    }

    __half* dst = g_Pp + ((size_t)(ch * Bn + b) * Jn) * Cn;
    int j0 = w * 16 + gid;
#pragma unroll
    for (int nt = 0; nt < 8; nt++) {
        *(uint32_t*)&dst[j0 * Cn + nt * 8 + 2 * tg]       = f2h2(c[nt][0], c[nt][1]);
        *(uint32_t*)&dst[(j0 + 8) * Cn + nt * 8 + 2 * tg] = f2h2(c[nt][2], c[nt][3]);
    }
}

// ---------------------------------------------------------------------------
// Stage 2: fused partial-reduce + complex mix.  256 thr = 4 modes x 64 o.
// ---------------------------------------------------------------------------
__global__ void __launch_bounds__(256) k_mix() {
    int kq = threadIdx.x >> 6, o = threadIdx.x & 63;
    int k = blockIdx.x * 4 + kq, b = blockIdx.y;
    __shared__ float P0[4][Cn], P1[4][Cn];
    float p0 = 0.0f, p1 = 0.0f;
#pragma unroll 4
    for (int ch = 0; ch < NCH; ch++) {
        const __half* src = g_Pp + ((size_t)(ch * Bn + b) * Jn + 2 * k) * Cn;
        p0 += __half2float(src[o]);
        p1 += __half2float(src[Cn + o]);
    }
    P0[kq][o] = p0; P1[kq][o] = p1;
    __syncthreads();
    float gr = 0.0f, gi = 0.0f;
#pragma unroll 8
    for (int i = 0; i < Cn; i++) {
        float a  = g_Aw[(k * Cn + i) * Cn + o];
        float bb = g_Bw[(k * Cn + i) * Cn + o];
        float pr = P0[kq][i], pi = P1[kq][i];
        gr += pr * a + pi * bb;
        gi += pi * a - pr * bb;
    }
    g_G[(b * JG + 2 * k) * Cn + o]     = gr;
    g_G[(b * JG + 2 * k + 1) * Cn + o] = gi;
}

// ---------------------------------------------------------------------------
// Stage 3: out[l=128][o=64] = sum_{j<192} bigA[l,j]*G[j,o] + bias; fp16 MMA.
// Warp grid 4(M) x 2(N): each ldmatrix B result feeds 4 MMAs (2 m-tiles x 2 n).
// B-ldsm per warp: 24 (was 48).  Accums stay 32 regs.
// ---------------------------------------------------------------------------
__global__ void __launch_bounds__(256, 4) k_out(const float* __restrict__ x,
                                                const float* __restrict__ bias,
                                                float* __restrict__ out) {
    int lt = blockIdx.x, b = blockIdx.y;
    __shared__ __align__(16) __half Gs[JG * SH];
    __shared__ __align__(16) __half As[128 * SH];
    int t = threadIdx.x, w = t >> 5, lane = t & 31;
    int wm = w & 3, wn = w >> 2;
    int gid = lane >> 2, tg = lane & 3;
    uint32_t gs0 = s2u(Gs);
    uint32_t laneB = ((((lane >> 3) & 1) * 8 + (lane & 7)) * SH + ((lane >> 4) & 1) * 8) * 2;
    uint32_t colB = (wn * 32) * 2;               // byte offset of warp's N strip

    {   // stage G (fp32 -> fp16): 3072 float4
        const float4* src = (const float4*)(g_G + (size_t)b * JG * Cn);
#pragma unroll
        for (int i = 0; i < 12; i++) {
            int idx = t + i * 256;
            int j = idx >> 4, cc = idx & 15;
            *(uint2*)&Gs[j * SH + cc * 4] = f4h4(src[idx]);
        }
        const float4* xs = (const float4*)(x + ((size_t)b * Ln + lt * 128) * Cn);
#pragma unroll
        for (int i = 0; i < 8; i++) {            // stage x: 2048 float4
            int idx = t + i * 256;
            int r = idx >> 4, cc = idx & 15;
            *(uint2*)&As[r * SH + cc * 4] = f4h4(xs[idx]);
        }
    }
    __syncthreads();

    float c[2][4][4];                            // [mt][nt][q] = 32 regs
#pragma unroll
    for (int mt = 0; mt < 2; mt++)
#pragma unroll
        for (int nt = 0; nt < 4; nt++)
#pragma unroll
            for (int q = 0; q < 4; q++) c[mt][nt][q] = 0.0f;

    const uint4* ap0 = g_b3frag + ((size_t)(lt * 8 + 2 * wm)) * 8 * 32 + lane;
    const uint4* ap1 = ap0 + 8 * 32;
#pragma unroll
    for (int ks = 0; ks < 8; ks++) {             // basis part (K 0..127)
        uint4 af0 = ap0[ks * 32];
        uint4 af1 = ap1[ks * 32];
        uint32_t a0[4] = { af0.x, af0.y, af0.z, af0.w };
        uint32_t a1[4] = { af1.x, af1.y, af1.z, af1.w };
        uint32_t stepB = gs0 + laneB + colB + ks * (16 * SH * 2);
#pragma unroll
        for (int p = 0; p < 2; p++) {
            uint32_t br[4];
            ldmat4t(br, stepB + p * 32);
            mma16(c[0][2 * p],     a0, br[0], br[1]);
            mma16(c[0][2 * p + 1], a0, br[2], br[3]);
            mma16(c[1][2 * p],     a1, br[0], br[1]);
            mma16(c[1][2 * p + 1], a1, br[2], br[3]);
        }
    }
#pragma unroll
    for (int ks = 0; ks < 4; ks++) {             // x part (K 128..191)
        int kk = ks * 16 + 2 * tg;
        int r0 = wm * 32 + gid;
        uint32_t a0[4], a1[4];
        a0[0] = *(const uint32_t*)&As[r0 * SH + kk];
        a0[1] = *(const uint32_t*)&As[(r0 + 8) * SH + kk];
        a0[2] = *(const uint32_t*)&As[r0 * SH + kk + 8];
        a0[3] = *(const uint32_t*)&As[(r0 + 8) * SH + kk + 8];
        a1[0] = *(const uint32_t*)&As[(r0 + 16) * SH + kk];
        a1[1] = *(const uint32_t*)&As[(r0 + 24) * SH + kk];
        a1[2] = *(const uint32_t*)&As[(r0 + 16) * SH + kk + 8];
        a1[3] = *(const uint32_t*)&As[(r0 + 24) * SH + kk + 8];
        uint32_t stepB = gs0 + laneB + colB + (128 + ks * 16) * (SH * 2);
#pragma unroll
        for (int p = 0; p < 2; p++) {
            uint32_t br[4];
            ldmat4t(br, stepB + p * 32);
            mma16(c[0][2 * p],     a0, br[0], br[1]);
            mma16(c[0][2 * p + 1], a0, br[2], br[3]);
            mma16(c[1][2 * p],     a1, br[0], br[1]);
            mma16(c[1][2 * p + 1], a1, br[2], br[3]);
        }
    }

#pragma unroll
    for (int mt = 0; mt < 2; mt++) {
        int l0 = lt * 128 + wm * 32 + mt * 16 + gid;
        float* dst = out + ((size_t)b * Ln + l0) * Cn;
#pragma unroll
        for (int nt = 0; nt < 4; nt++) {
            int col = wn * 32 + nt * 8 + 2 * tg;
            float2 bb = *(const float2*)&bias[col];
            *(float2*)&dst[col] =
                make_float2(c[mt][nt][0] + bb.x, c[mt][nt][1] + bb.y);
            *(float2*)&dst[8 * Cn + col] =
                make_float2(c[mt][nt][2] + bb.x, c[mt][nt][3] + bb.y);
        }
    }
}

// ---------------------------------------------------------------------------
extern "C" void kernel_launch(void* const* d_in, const int* in_sizes, int n_in,
                              void* d_out, int out_size) {
    const float* x    = (const float*)d_in[0];
    const float* wr   = (const float*)d_in[1];
    const float* wi   = (const float*)d_in[2];
    const float* pw   = (const float*)d_in[3];
    const float* bias = (const float*)d_in[4];
    float* out = (float*)d_out;

    k_prep<<<1312, 256>>>(wr, wi, pw);
    k_dft<<<dim3(NCH, Bn), 256>>>(x);
    k_mix<<<dim3(Mn / 4, Bn), 256>>>();
    k_out<<<dim3(Ln / 128, Bn), 256>>>(x, bias, out);
}